// round 17
// baseline (speedup 1.0000x reference)
#include <cuda_runtime.h>
#include <cstdint>

// ---------------------------------------------------------------------------
// Round 16: split-K=2. Grid (256 tiles x 2 k-halves) = 512 CTAs; each writes
//   raw partial h_pre (32x64) + partial sumsq to g_part/g_ssp. Epilogue kernel
//   combines halves + H_st, applies rmsnorm/relu/final-layer/sigmoid.
//   Rationale: 256 CTAs @2/SM leaves 40 SMs half-loaded; 512 finer CTAs
//   backfill dynamically. Main-loop code otherwise byte-equivalent to R15.
// ---------------------------------------------------------------------------

#define MPTS   32
#define TPB    256
#define KC     128
#define KPAD   9600
#define NCHT   75            // total chunks
#define NCH0   38            // khalf 0: chunks [0,38)
#define NCH1   37            // khalf 1: chunks [38,75)
#define SA     132
#define RS     72
#define NK8    (KPAD / 8)
#define NB     28
#define NCOMBO 960
#define NPTS   8192
#define STK    2720
#define WF4_N  (NK8 * 4 * 32)
#define WST_N  (STK * 16)

__device__ uint4 g_Wf4[NK8 * 4 * 32];
__device__ float g_Wst[STK * 64];
__device__ float g_Hst[NCOMBO * 64];
__device__ float g_SSst[NCOMBO];
__device__ int   g_live[NCOMBO];
__device__ float g_part[2 * NPTS * 64];   // raw partial h_pre per khalf
__device__ float g_ssp[2 * NPTS];         // raw partial sumsq per khalf

__constant__ int c_OFF7[7][3] = {
    {0,0,0},{1,0,0},{-1,0,0},{0,1,0},{0,-1,0},{0,0,1},{0,0,-1}};
__constant__ int c_S14[14][3] = {
    {1,0,0},{-1,0,0},{0,1,0},{0,-1,0},{0,0,1},{0,0,-1},
    {1,1,1},{-1,-1,-1},{1,-1,-1},{-1,1,1},{1,1,-1},{-1,-1,1},{1,-1,1},{-1,1,-1}};
__constant__ int c_CORNER[8][3] = {
    {1,1,1},{-1,-1,-1},{1,-1,-1},{-1,1,1},{1,1,-1},{-1,-1,1},{1,-1,1},{-1,1,-1}};
__constant__ int c_ETEMP[11] = {-64,-8,-4,-2,-1,0,1,2,4,8,64};

__device__ __forceinline__ uint32_t f2tf32(float x) {
    uint32_t u;
    asm("cvt.rna.tf32.f32 %0, %1;" : "=r"(u) : "f"(x));
    return u;
}

__device__ __forceinline__ uint32_t s2u(const void* p) {
    uint32_t a;
    asm("{ .reg .u64 t; cvta.to.shared.u64 t, %1; cvt.u32.u64 %0, t; }"
        : "=r"(a) : "l"(p));
    return a;
}

__device__ __forceinline__ void mma8(float* c,
                                     uint32_t a0, uint32_t a1, uint32_t a2, uint32_t a3,
                                     uint32_t b0, uint32_t b1) {
    asm("mma.sync.aligned.m16n8k8.row.col.f32.tf32.tf32.f32 "
        "{%0,%1,%2,%3}, {%4,%5,%6,%7}, {%8,%9}, {%0,%1,%2,%3};"
        : "+f"(c[0]), "+f"(c[1]), "+f"(c[2]), "+f"(c[3])
        : "r"(a0), "r"(a1), "r"(a2), "r"(a3), "r"(b0), "r"(b1));
}

// ---------------------------------------------------------------------------
__global__ void __launch_bounds__(256)
wf_precompute_kernel(const float* __restrict__ w_down,
                     const float* __restrict__ rms_scale,
                     const float* __restrict__ d_t)
{
    int T = blockIdx.x * 256 + threadIdx.x;
    if (T < WF4_N) {
        int lane = T & 31;
        int nt2  = (T >> 5) & 3;
        int K8   = T >> 7;
        int ne = nt2 * 16 + (lane >> 2);
        int no = ne + 8;
        int k0 = K8 * 8 + (lane & 3);
        int k1 = k0 + 4;
        uint4 u;
        u.x = (k0 < 9520) ? f2tf32(w_down[k0 * 64 + ne] * rms_scale[k0]) : 0u;
        u.y = (k1 < 9520) ? f2tf32(w_down[k1 * 64 + ne] * rms_scale[k1]) : 0u;
        u.z = (k0 < 9520) ? f2tf32(w_down[k0 * 64 + no] * rms_scale[k0]) : 0u;
        u.w = (k1 < 9520) ? f2tf32(w_down[k1 * 64 + no] * rms_scale[k1]) : 0u;
        g_Wf4[T] = u;
    } else if (T < WF4_N + WST_N) {
        int idx = T - WF4_N;
        int kk  = idx >> 4;
        int n4  = (idx & 15) << 2;
        int k   = 9520 + kk;
        float s = rms_scale[k];
        float4 w = *reinterpret_cast<const float4*>(w_down + k * 64 + n4);
        float4 o;
        o.x = __uint_as_float(f2tf32(w.x * s));
        o.y = __uint_as_float(f2tf32(w.y * s));
        o.z = __uint_as_float(f2tf32(w.z * s));
        o.w = __uint_as_float(f2tf32(w.w * s));
        *reinterpret_cast<float4*>(g_Wst + kk * 64 + n4) = o;
    } else if (T < WF4_N + WST_N + NPTS) {
        float tv = d_t[T - WF4_N - WST_N];
        int key = ((int)(tv * 15.0f)) * 64 + (int)(tv * 63.0f);
        g_live[key] = 1;
    }
}

// ---------------------------------------------------------------------------
__global__ void __launch_bounds__(256)
st_precompute_kernel(const float* __restrict__ S1t,
                     const float* __restrict__ S2t,
                     const float* __restrict__ TF)
{
    __shared__ int   gbase[144];
    __shared__ float fst[STK];
    __shared__ float red[256];

    int c = blockIdx.x;
    if (!g_live[c]) return;
    int tb = c >> 6, tvv = c & 63;
    int tid = threadIdx.x;

    if (tid < 144) {
        int g = tid, b;
        if (g < 28) {
            int si = g >> 1; int tt = (g & 1) ? -1 : 1;
            int a  = (tb + c_S14[si][0] + 16) & 15;
            int bb = (tb + c_S14[si][1] + 16) & 15;
            int cc = (tb + c_S14[si][2] + 16) & 15;
            int dd = (tvv + tt + 64) & 63;
            b = (((((((a << 4) | bb) << 4) | cc) << 6) | dd) << 6);
        } else if (g < 56) {
            int gg = g - 28; int si = gg >> 1; int tt = (gg & 1) ? -1 : 1;
            int a  = (tb + c_S14[si][0] + 64) & 63;
            int bb = (tb + c_S14[si][1] + 64) & 63;
            int cc = (tb + c_S14[si][2] + 64) & 63;
            int dd = (tvv + tt + 64) & 63;
            b = (((((((a << 6) | bb) << 6) | cc) << 6) | dd) << 3);
        } else {
            int gg = g - 56; int ci = gg / 11, ti = gg - ci * 11;
            int a  = (tb + c_CORNER[ci][0] + 4) & 3;
            int bb = (tb + c_CORNER[ci][1] + 4) & 3;
            int cc = (tb + c_CORNER[ci][2] + 4) & 3;
            int dd = (tvv + c_ETEMP[ti] + 65536) & 65535;
            b = (((((((a << 2) | bb) << 2) | cc) << 16) | dd) << 3);
        }
        gbase[g] = b;
    }
    __syncthreads();

    float ssp = 0.f;
    for (int e4 = tid; e4 < STK / 4; e4 += 256) {
        int r = e4 << 2;
        const float* fp;
        if (r < 1792)      fp = S1t + gbase[r >> 6] + (r & 63);
        else if (r < 2016) { int rr = r - 1792; fp = S2t + gbase[28 + (rr >> 3)] + (rr & 7); }
        else               { int rr = r - 2016; fp = TF  + gbase[56 + (rr >> 3)] + (rr & 7); }
        float4 v = *reinterpret_cast<const float4*>(fp);
        v.x = fmaxf(v.x, 0.f); v.y = fmaxf(v.y, 0.f);
        v.z = fmaxf(v.z, 0.f); v.w = fmaxf(v.w, 0.f);
        ssp += v.x * v.x + v.y * v.y + v.z * v.z + v.w * v.w;
        fst[r + 0] = __uint_as_float(__float_as_uint(v.x) & 0xFFFFE000u);
        fst[r + 1] = __uint_as_float(__float_as_uint(v.y) & 0xFFFFE000u);
        fst[r + 2] = __uint_as_float(__float_as_uint(v.z) & 0xFFFFE000u);
        fst[r + 3] = __uint_as_float(__float_as_uint(v.w) & 0xFFFFE000u);
    }
    red[tid] = ssp;
    __syncthreads();
    for (int s = 128; s > 0; s >>= 1) {
        if (tid < s) red[tid] += red[tid + s];
        __syncthreads();
    }
    float ssT = red[0];
    __syncthreads();

    int n  = tid & 63;
    int sl = tid >> 6;
    int k0 = sl * (STK / 4);
    float acc = 0.f;
#pragma unroll 8
    for (int j = 0; j < STK / 4; j++) {
        acc += fst[k0 + j] * g_Wst[(k0 + j) * 64 + n];
    }
    red[tid] = acc;
    __syncthreads();
    if (sl == 0) {
        g_Hst[c * 64 + n] = red[n] + red[64 + n] + red[128 + n] + red[192 + n];
        if (n == 0) g_SSst[c] = ssT;
    }
}

// ---------------------------------------------------------------------------
__device__ __forceinline__ float4 gather4b(
    int k, const int* __restrict__ bp,
    const float* __restrict__ T0, const float* __restrict__ T1,
    const float* __restrict__ T2, const float* __restrict__ T3)
{
    if (k < 9520) {
        const float* tab; int r, flog, bi;
        if (k < 112)       { tab = T0; r = k;        flog = 4;  bi = 0;  }
        else if (k < 560)  { tab = T1; r = k - 112;  flog = 6;  bi = 7;  }
        else if (k < 2352) { tab = T2; r = k - 560;  flog = 8;  bi = 14; }
        else               { tab = T3; r = k - 2352; flog = 10; bi = 21; }
        int o = r >> flog;
        int f = r & ((1 << flog) - 1);
        return *reinterpret_cast<const float4*>(tab + bp[bi + o] + f);
    }
    return make_float4(0.f, 0.f, 0.f, 0.f);
}

// ---------------------------------------------------------------------------
__global__ void __launch_bounds__(TPB, 2)
stlt_fused_kernel(
    const float* __restrict__ d_pos, const float* __restrict__ d_t,
    const float* __restrict__ T0, const float* __restrict__ T1,
    const float* __restrict__ T2, const float* __restrict__ T3)
{
    __shared__ alignas(16) uint32_t As[2 * MPTS * SA];
    __shared__ alignas(16) float    Rbuf[MPTS * RS];
    __shared__ int      bases[MPTS * NB];
    __shared__ int      pidx[MPTS][12];

    const int tid  = threadIdx.x;
    const int lane = tid & 31;
    const int warp = tid >> 5;
    const int kq   = warp >> 1;
    const int nh   = warp & 1;
    const int p0   = blockIdx.x * MPTS;
    const int kh   = blockIdx.y;                   // k-half
    const int chb  = kh ? NCH0 : 0;                // chunk base
    const int nch  = kh ? NCH1 : NCH0;

    if (tid < MPTS) {
        int gp = p0 + tid;
        float px = d_pos[gp * 3 + 0];
        float py = d_pos[gp * 3 + 1];
        float pz = d_pos[gp * 3 + 2];
        pidx[tid][0]  = (int)(px * 127.0f);
        pidx[tid][1]  = (int)(py * 127.0f);
        pidx[tid][2]  = (int)(pz * 127.0f);
        pidx[tid][3]  = (int)(px * 63.0f);
        pidx[tid][4]  = (int)(py * 63.0f);
        pidx[tid][5]  = (int)(pz * 63.0f);
        pidx[tid][6]  = (int)(px * 31.0f);
        pidx[tid][7]  = (int)(py * 31.0f);
        pidx[tid][8]  = (int)(pz * 31.0f);
        pidx[tid][9]  = (int)(px * 15.0f);
        pidx[tid][10] = (int)(py * 15.0f);
        pidx[tid][11] = (int)(pz * 15.0f);
    }
    __syncthreads();

    for (int e = tid; e < MPTS * NB; e += TPB) {
        int p = e / NB;
        int j = e - p * NB;
        int tau  = j / 7;
        int o    = j - tau * 7;
        int dlog = 7 - tau;
        int flog = 4 + 2 * tau;
        int d = 1 << dlog, m = d - 1;
        int cx = (pidx[p][tau * 3 + 0] + c_OFF7[o][0] + d) & m;
        int cy = (pidx[p][tau * 3 + 1] + c_OFF7[o][1] + d) & m;
        int cz = (pidx[p][tau * 3 + 2] + c_OFF7[o][2] + d) & m;
        bases[e] = ((((cx << dlog) | cy) << dlog) | cz) << flog;
    }
    __syncthreads();

    float acc[2][4][4];
#pragma unroll
    for (int m = 0; m < 2; m++)
#pragma unroll
        for (int i = 0; i < 4; i++)
#pragma unroll
            for (int j = 0; j < 4; j++) acc[m][i][j] = 0.f;
    float ss[4] = {0.f, 0.f, 0.f, 0.f};

    const int lm_row = ((lane >> 3) & 1) * 8 + (lane & 7);
    const int lm_kof = (lane >> 4) * 4;

    const uint4* Wch = g_Wf4 + (size_t)chb * 2048
                     + ((size_t)(kq * 4) << 7) + (2 * nh) * 32 + lane;

    float4 v[4];
#pragma unroll
    for (int j = 0; j < 4; j++) {
        int i  = tid + j * TPB;
        int p  = i >> 5;
        int k4 = (i & 31) << 2;
        v[j] = gather4b(chb * KC + k4, bases + p * NB, T0, T1, T2, T3);
    }

    for (int ch = 0; ch < nch; ch++) {
        uint32_t* buf = As + (ch & 1) * (MPTS * SA);
        const int kb  = (chb + ch) * KC;

#pragma unroll
        for (int j = 0; j < 4; j++) {
            float4 w = v[j];
            w.x = fmaxf(w.x, 0.f); w.y = fmaxf(w.y, 0.f);
            w.z = fmaxf(w.z, 0.f); w.w = fmaxf(w.w, 0.f);
            ss[j] += w.x * w.x + w.y * w.y + w.z * w.z + w.w * w.w;
            int i = tid + j * TPB;
            *reinterpret_cast<float4*>(&buf[(i >> 5) * SA + ((i & 31) << 2)]) = w;
        }
        __syncthreads();

        if (ch + 1 < nch) {
#pragma unroll
            for (int j = 0; j < 4; j++) {
                int i  = tid + j * TPB;
                int p  = i >> 5;
                int k4 = (i & 31) << 2;
                v[j] = gather4b(kb + KC + k4, bases + p * NB, T0, T1, T2, T3);
            }
        }

#pragma unroll
        for (int g = 0; g < 4; g++) {
            int kk = (kq * 4 + g) * 8;
            uint4 bq0 = Wch[g * 128];
            uint4 bq1 = Wch[g * 128 + 32];
#pragma unroll
            for (int mt = 0; mt < 2; mt++) {
                uint32_t a0, a1, a2, a3;
                uint32_t addr = s2u(&buf[(mt * 16 + lm_row) * SA + kk + lm_kof]);
                asm volatile("ldmatrix.sync.aligned.m8n8.x4.shared.b16 {%0,%1,%2,%3}, [%4];"
                             : "=r"(a0), "=r"(a1), "=r"(a2), "=r"(a3) : "r"(addr));
                mma8(acc[mt][0], a0, a1, a2, a3, bq0.x, bq0.y);
                mma8(acc[mt][1], a0, a1, a2, a3, bq0.z, bq0.w);
                mma8(acc[mt][2], a0, a1, a2, a3, bq1.x, bq1.y);
                mma8(acc[mt][3], a0, a1, a2, a3, bq1.z, bq1.w);
            }
        }
        Wch += 2048;
    }

    // ---- sumsq: warp reduce, raw partial to global ------------------------
#pragma unroll
    for (int s = 16; s >= 1; s >>= 1) {
#pragma unroll
        for (int j = 0; j < 4; j++)
            ss[j] += __shfl_xor_sync(0xffffffffu, ss[j], s);
    }
    if (lane == 0) {
#pragma unroll
        for (int j = 0; j < 4; j++)
            g_ssp[kh * NPTS + p0 + warp + 8 * j] = ss[j];
    }

    // ---- cross-kq reduction -> raw partial h_pre to global ----------------
    {
        int row = lane >> 2;
        int cb  = nh * 32 + (lane & 3) * 2;
        if (kq == 3) {
#pragma unroll
            for (int mt = 0; mt < 2; mt++)
#pragma unroll
            for (int nt = 0; nt < 4; nt++) {
                int col = cb + nt * 8;
                int r0 = mt * 16 + row;
                Rbuf[r0 * RS + col]           = acc[mt][nt][0];
                Rbuf[r0 * RS + col + 1]       = acc[mt][nt][1];
                Rbuf[(r0 + 8) * RS + col]     = acc[mt][nt][2];
                Rbuf[(r0 + 8) * RS + col + 1] = acc[mt][nt][3];
            }
        }
        __syncthreads();
        if (kq == 2) {
#pragma unroll
            for (int mt = 0; mt < 2; mt++)
#pragma unroll
            for (int nt = 0; nt < 4; nt++) {
                int col = cb + nt * 8;
                int r0 = mt * 16 + row;
                Rbuf[r0 * RS + col]           += acc[mt][nt][0];
                Rbuf[r0 * RS + col + 1]       += acc[mt][nt][1];
                Rbuf[(r0 + 8) * RS + col]     += acc[mt][nt][2];
                Rbuf[(r0 + 8) * RS + col + 1] += acc[mt][nt][3];
            }
        }
        __syncthreads();
        if (kq == 1) {
#pragma unroll
            for (int mt = 0; mt < 2; mt++)
#pragma unroll
            for (int nt = 0; nt < 4; nt++) {
                int col = cb + nt * 8;
                int r0 = mt * 16 + row;
                Rbuf[r0 * RS + col]           += acc[mt][nt][0];
                Rbuf[r0 * RS + col + 1]       += acc[mt][nt][1];
                Rbuf[(r0 + 8) * RS + col]     += acc[mt][nt][2];
                Rbuf[(r0 + 8) * RS + col + 1] += acc[mt][nt][3];
            }
        }
        __syncthreads();
        if (kq == 0) {
#pragma unroll
            for (int mt = 0; mt < 2; mt++) {
                int r0 = mt * 16 + row;
                int r1 = r0 + 8;
                float* P0 = g_part + ((size_t)(kh * NPTS + p0 + r0)) * 64;
                float* P1 = g_part + ((size_t)(kh * NPTS + p0 + r1)) * 64;
#pragma unroll
                for (int nt = 0; nt < 4; nt++) {
                    int col = cb + nt * 8;
                    float2 u0, u1;
                    u0.x = acc[mt][nt][0] + Rbuf[r0 * RS + col];
                    u0.y = acc[mt][nt][1] + Rbuf[r0 * RS + col + 1];
                    u1.x = acc[mt][nt][2] + Rbuf[r1 * RS + col];
                    u1.y = acc[mt][nt][3] + Rbuf[r1 * RS + col + 1];
                    *reinterpret_cast<float2*>(P0 + col) = u0;
                    *reinterpret_cast<float2*>(P1 + col) = u1;
                }
            }
        }
    }
}

// ---------------------------------------------------------------------------
// Epilogue: combine k-halves + ST part, rmsnorm, relu, final layer, sigmoid.
__global__ void __launch_bounds__(256)
epilogue_kernel(const float* __restrict__ d_dir, const float* __restrict__ d_t,
                const float* __restrict__ w_final, const float* __restrict__ b_final,
                float* __restrict__ d_out)
{
    int gp = blockIdx.x * 256 + threadIdx.x;
    if (gp >= NPTS) return;
    float tv = d_t[gp];
    int key = ((int)(tv * 15.0f)) * 64 + (int)(tv * 63.0f);
    float ssv = g_ssp[gp] + g_ssp[NPTS + gp] + g_SSst[key];
    float inv = 1.0f / (sqrtf(ssv * (1.0f / 12240.0f)) + 1e-8f);

    const float4* P0 = reinterpret_cast<const float4*>(g_part + (size_t)gp * 64);
    const float4* P1 = reinterpret_cast<const float4*>(g_part + (size_t)(NPTS + gp) * 64);
    const float4* Hs = reinterpret_cast<const float4*>(g_Hst + key * 64);

    float o0 = b_final[0], o1 = b_final[1], o2 = b_final[2], o3 = b_final[3];
#pragma unroll
    for (int i4 = 0; i4 < 16; i4++) {
        float4 a = P0[i4], b = P1[i4], hh = Hs[i4];
        float h0 = fmaxf((a.x + b.x + hh.x) * inv, 0.f);
        float h1 = fmaxf((a.y + b.y + hh.y) * inv, 0.f);
        float h2 = fmaxf((a.z + b.z + hh.z) * inv, 0.f);
        float h3 = fmaxf((a.w + b.w + hh.w) * inv, 0.f);
        float4 w0 = *reinterpret_cast<const float4*>(w_final + (i4 * 4 + 0) * 4);
        float4 w1 = *reinterpret_cast<const float4*>(w_final + (i4 * 4 + 1) * 4);
        float4 w2 = *reinterpret_cast<const float4*>(w_final + (i4 * 4 + 2) * 4);
        float4 w3 = *reinterpret_cast<const float4*>(w_final + (i4 * 4 + 3) * 4);
        o0 += h0 * w0.x + h1 * w1.x + h2 * w2.x + h3 * w3.x;
        o1 += h0 * w0.y + h1 * w1.y + h2 * w2.y + h3 * w3.y;
        o2 += h0 * w0.z + h1 * w1.z + h2 * w2.z + h3 * w3.z;
        o3 += h0 * w0.w + h1 * w1.w + h2 * w2.w + h3 * w3.w;
    }
#pragma unroll
    for (int c = 0; c < 3; c++) {
        float dv = d_dir[gp * 3 + c];
        float4 wf = *reinterpret_cast<const float4*>(w_final + (64 + c) * 4);
        o0 += dv * wf.x; o1 += dv * wf.y; o2 += dv * wf.z; o3 += dv * wf.w;
    }
    {
        float4 wf = *reinterpret_cast<const float4*>(w_final + 67 * 4);
        o0 += tv * wf.x; o1 += tv * wf.y; o2 += tv * wf.z; o3 += tv * wf.w;
    }
    float4 r;
    r.x = 1.0f / (1.0f + expf(-o0));
    r.y = 1.0f / (1.0f + expf(-o1));
    r.z = 1.0f / (1.0f + expf(-o2));
    r.w = 1.0f / (1.0f + expf(-o3));
    *reinterpret_cast<float4*>(d_out + gp * 4) = r;
}

extern "C" void kernel_launch(void* const* d_in, const int* in_sizes, int n_in,
                              void* d_out, int out_size) {
    const float* pos       = (const float*)d_in[0];
    const float* dirv      = (const float*)d_in[1];
    const float* t         = (const float*)d_in[2];
    const float* table0    = (const float*)d_in[3];
    const float* table1    = (const float*)d_in[4];
    const float* table2    = (const float*)d_in[5];
    const float* table3    = (const float*)d_in[6];
    const float* st1       = (const float*)d_in[7];
    const float* st2       = (const float*)d_in[8];
    const float* tf3       = (const float*)d_in[9];
    const float* rms_scale = (const float*)d_in[10];
    const float* w_down    = (const float*)d_in[11];
    const float* w_final   = (const float*)d_in[12];
    const float* b_final   = (const float*)d_in[13];
    float* out = (float*)d_out;

    wf_precompute_kernel<<<(WF4_N + WST_N + NPTS + 255) / 256, 256>>>(w_down, rms_scale, t);
    st_precompute_kernel<<<NCOMBO, 256>>>(st1, st2, tf3);
    stlt_fused_kernel<<<dim3(NPTS / MPTS, 2), TPB>>>(pos, t, table0, table1, table2, table3);
    epilogue_kernel<<<(NPTS + 255) / 256, 256>>>(dirv, t, w_final, b_final, out);
}